// round 3
// baseline (speedup 1.0000x reference)
#include <cuda_runtime.h>
#include <cuda_bf16.h>

// src [8,16,512,512] f32, flow [8,2,512,512] f32, out [8,16,512,512] f32.
//
// Reproduce XLA's lowering of the reference bit-exactly:
//   XLA rewrites x/(H-1) into x * fp32(1/(H-1))  (reciprocal-constant rewrite).
// Chain (each step fp32-rounded, no FMA contraction):
//   t = h + f;  t = t * (1/511);  t = t - 0.5;  t = 2*t;  t = t+1; t = t*0.5; t = t*511
//   idx = rint(t) (half-to-even), clamp [0,511].
// Note ×2.0 and ×0.5 are exact, so folded/unfolded constant-multiply forms are
// bit-identical; the division was the only ambiguous op.
// Then out[b,c,h,w] = src[b,c,yi,xi] for all 16 channels (index reused 16x).

#define B 8
#define C 16
#define H 512
#define W 512
#define HW (H * W)          // 262144 = 1<<18
#define HW_BITS 18
#define W_BITS 9

__device__ __forceinline__ int ref_index(float coord, float disp, float dim_m1, float rcp)
{
    float t = __fadd_rn(coord, disp);        // ii + flow
    t = __fmul_rn(t, rcp);                   // * fp32(1/(H-1))   (XLA recip rewrite)
    t = __fadd_rn(t, -0.5f);                 // - 0.5
    t = __fmul_rn(2.0f, t);                  // * 2  (exact)
    t = __fadd_rn(t, 1.0f);                  // n + 1
    t = __fmul_rn(t, 0.5f);                  // * 0.5 (exact)
    t = __fmul_rn(t, dim_m1);                // * (H-1)
    int i = __float2int_rn(t);               // round half-to-even
    return min(max(i, 0), (int)dim_m1);      // border clamp
}

__global__ __launch_bounds__(256) void flow_warp_nearest_kernel(
    const float* __restrict__ src,
    const float* __restrict__ flow,
    float* __restrict__ out)
{
    int idx = blockIdx.x * blockDim.x + threadIdx.x;   // over B*H*W = 2M
    if (idx >= B * HW) return;

    int b  = idx >> HW_BITS;
    int hw = idx & (HW - 1);
    int h  = hw >> W_BITS;
    int w  = hw & (W - 1);

    const float* fb = flow + (size_t)b * 2 * HW;
    float f0 = __ldg(fb + hw);          // row displacement
    float f1 = __ldg(fb + HW + hw);     // col displacement

    const float rcp = 1.0f / 511.0f;    // correctly-rounded fp32 constant (host-folded)

    int yi = ref_index((float)h, f0, (float)(H - 1), rcp);
    int xi = ref_index((float)w, f1, (float)(W - 1), rcp);
    int lin = (yi << W_BITS) + xi;

    const float* sb = src + (size_t)b * C * HW;
    float*       ob = out + (size_t)b * C * HW;

    #pragma unroll
    for (int c = 0; c < C; ++c) {
        ob[c * HW + hw] = __ldg(sb + c * HW + lin);
    }
}

extern "C" void kernel_launch(void* const* d_in, const int* in_sizes, int n_in,
                              void* d_out, int out_size)
{
    const float* src  = (const float*)d_in[0];
    const float* flow = (const float*)d_in[1];
    float*       out  = (float*)d_out;

    int total = B * HW;                 // 2,097,152 threads
    int threads = 256;
    int blocks = (total + threads - 1) / threads;   // 8192
    flow_warp_nearest_kernel<<<blocks, threads>>>(src, flow, out);
}